// round 15
// baseline (speedup 1.0000x reference)
#include <cuda_runtime.h>
#include <cuda_bf16.h>
#include <cuda_fp16.h>
#include <cstdint>

#define HF 128
#define MAX_NODES 100000

// Per-node precomputed layer-1 partials, fp16, b1 folded into A part:
// C[n][0:64] = h[n] @ W1[:, :128].T + b1 ; C[n][64:128] = h[n] @ W1[:, 128:].T
__device__ uint32_t g_C[(size_t)MAX_NODES * 64];
// Fragment tables (fp16 half2):
//   g_Bh : m16n8k16 B-frag order  ((nt*8+kt)*2+r)*32 + l   (precompute SMEM copy)
//   g_W2h: PAIR layout (nt*4+kt)*64 + l*2 + r              (edge, uint2 loads)
//   g_W3h: PAIR layout kt*64 + l*2 + r                     (edge, uint2 loads)
// Element law: j = nt*8+(l>>2), kk = kt*16 + 2*(l&3) + r*8
__device__ uint32_t g_Bh[8192];
__device__ uint32_t g_W2h[1024];
__device__ uint32_t g_W3h[128];

__device__ __forceinline__ void mma_f16(float& c0, float& c1, float& c2, float& c3,
                                        uint32_t a0, uint32_t a1, uint32_t a2, uint32_t a3,
                                        uint32_t b0, uint32_t b1) {
    asm volatile(
        "mma.sync.aligned.m16n8k16.row.col.f32.f16.f16.f32 "
        "{%0,%1,%2,%3}, {%4,%5,%6,%7}, {%8,%9}, {%0,%1,%2,%3};"
        : "+f"(c0), "+f"(c1), "+f"(c2), "+f"(c3)
        : "r"(a0), "r"(a1), "r"(a2), "r"(a3), "r"(b0), "r"(b1));
}

__device__ __forceinline__ void ldsm_x4(uint32_t& r0, uint32_t& r1,
                                        uint32_t& r2, uint32_t& r3, uint32_t addr) {
    asm volatile("ldmatrix.sync.aligned.m8n8.x4.shared.b16 {%0,%1,%2,%3}, [%4];"
                 : "=r"(r0), "=r"(r1), "=r"(r2), "=r"(r3) : "r"(addr));
}

__device__ __forceinline__ uint32_t hadd_relu(uint32_t a, uint32_t b) {
    __half2 s = __hadd2(*(__half2*)&a, *(__half2*)&b);
    s = __hmax2(s, __half2half2(__float2half(0.f)));
    return *(uint32_t*)&s;
}

__device__ __forceinline__ uint32_t pack_h2(float x, float y) {
    __half2 v = __floats2half2_rn(x, y);
    return *(uint32_t*)&v;
}

__device__ __forceinline__ uint32_t pack_relu(float x, float y) {
    return pack_h2(fmaxf(x, 0.f), fmaxf(y, 0.f));
}

// ---------------------------------------------------------------------------
// Kernel 0: build fragment tables once.
// ---------------------------------------------------------------------------
__global__ void init_frag_kernel(const float* __restrict__ W1,
                                 const float* __restrict__ W2,
                                 const float* __restrict__ W3)
{
    int idx = blockIdx.x * 256 + threadIdx.x;
    if (idx < 8192) {   // frag order: ((nt*8+kt)*2+r)*32 + l
        int l  = idx & 31;
        int r  = (idx >> 5) & 1;
        int kt = (idx >> 6) & 7;
        int nt = idx >> 9;
        int j  = nt * 8 + (l >> 2);
        int kk = kt * 16 + 2 * (l & 3) + r * 8;
        float v0, v1;
        if (j < 64) { v0 = W1[j * 256 + kk];              v1 = W1[j * 256 + kk + 1]; }
        else        { v0 = W1[(j - 64) * 256 + 128 + kk]; v1 = W1[(j - 64) * 256 + 128 + kk + 1]; }
        g_Bh[idx] = pack_h2(v0, v1);
    }
    if (idx < 1024) {   // pair layout: idx = (nt*4+kt)*64 + l*2 + r
        int r  = idx & 1;
        int l  = (idx >> 1) & 31;
        int kt = (idx >> 6) & 3;
        int nt = idx >> 8;
        int j  = nt * 8 + (l >> 2);
        int kk = kt * 16 + 2 * (l & 3) + r * 8;
        g_W2h[idx] = pack_h2(W2[j * 64 + kk], W2[j * 64 + kk + 1]);
    }
    if (idx < 128) {    // pair layout: idx = kt*64 + l*2 + r
        int r  = idx & 1;
        int l  = (idx >> 1) & 31;
        int kt = idx >> 6;
        int j  = l >> 2;                       // output class (pad 6,7 -> 0)
        int kk = kt * 16 + 2 * (l & 3) + r * 8;
        float v0 = (j < 6) ? W3[j * 32 + kk]     : 0.f;
        float v1 = (j < 6) ? W3[j * 32 + kk + 1] : 0.f;
        g_W3h[idx] = pack_h2(v0, v1);
    }
}

// ---------------------------------------------------------------------------
// Kernel 1: C = h @ G.T via fp16 mma, persistent blocks (Bh table copied to
// SMEM once per block; all mma operands from SMEM). b1 as accumulator init.
// (r10 structure — proven optimum.)
// ---------------------------------------------------------------------------
#define HS2 68
#define PRE_GRID 444   // 148 SMs * 3 blocks

__global__ __launch_bounds__(256, 3) void precompute_kernel(
    const float* __restrict__ h, const float* __restrict__ b1,
    int n_nodes, int n_tiles)
{
    extern __shared__ uint32_t smu[];
    uint32_t* hs = smu;              // [64][HS2] = 4352 uints
    uint32_t* Bh = smu + 64 * HS2;   // 8192 uints

    const int tid  = threadIdx.x;
    const int lane = tid & 31;
    const int w    = tid >> 5;

    // Copy Bh table once per block (coalesced uint4)
    {
        uint4* dstp = (uint4*)Bh;
        const uint4* srcp = (const uint4*)g_Bh;
        #pragma unroll
        for (int i = 0; i < 8; ++i)
            dstp[i * 256 + tid] = srcp[i * 256 + tid];
    }

    const int g  = lane >> 2;
    const int cA = lane & 3;

    // b1 fold (loop-invariant; A-part warps: w<4 -> cols 0..63)
    float bv0[2] = {0.f, 0.f}, bv1[2] = {0.f, 0.f};
    if (w < 4) {
        #pragma unroll
        for (int n = 0; n < 2; ++n) {
            int col = (2 * w + n) * 8 + 2 * cA;
            bv0[n] = b1[col];
            bv1[n] = b1[col + 1];
        }
    }

    for (int t = blockIdx.x; t < n_tiles; t += PRE_GRID) {
        const int nb = t * 64;
        __syncthreads();   // hs reusable (also orders Bh copy on 1st iter)

        // Stage 64 h rows as fp16
        #pragma unroll
        for (int i = 0; i < 8; ++i) {
            int idx = i * 256 + tid;
            int row = idx >> 5;
            int q   = idx & 31;
            int n   = nb + row;
            float4 v = make_float4(0.f, 0.f, 0.f, 0.f);
            if (n < n_nodes) v = ((const float4*)h)[(size_t)n * 32 + q];
            uint2 p = make_uint2(pack_h2(v.x, v.y), pack_h2(v.z, v.w));
            *(uint2*)(hs + row * HS2 + 2 * q) = p;
        }
        __syncthreads();

        float acc[4][2][4];
        #pragma unroll
        for (int m = 0; m < 4; ++m)
            #pragma unroll
            for (int n = 0; n < 2; ++n) {
                acc[m][n][0] = bv0[n]; acc[m][n][1] = bv1[n];
                acc[m][n][2] = bv0[n]; acc[m][n][3] = bv1[n];
            }

        #pragma unroll
        for (int kt = 0; kt < 8; ++kt) {
            uint32_t a[4][4];
            #pragma unroll
            for (int m = 0; m < 4; ++m) {
                int rA = m * 16 + g;
                a[m][0] = hs[rA * HS2 + kt * 8 + cA];
                a[m][1] = hs[(rA + 8) * HS2 + kt * 8 + cA];
                a[m][2] = hs[rA * HS2 + kt * 8 + cA + 4];
                a[m][3] = hs[(rA + 8) * HS2 + kt * 8 + cA + 4];
            }
            #pragma unroll
            for (int n = 0; n < 2; ++n) {
                int nt = 2 * w + n;
                uint32_t b0  = Bh[((nt * 8 + kt) * 2 + 0) * 32 + lane];
                uint32_t b1f = Bh[((nt * 8 + kt) * 2 + 1) * 32 + lane];
                #pragma unroll
                for (int m = 0; m < 4; ++m)
                    mma_f16(acc[m][n][0], acc[m][n][1], acc[m][n][2], acc[m][n][3],
                            a[m][0], a[m][1], a[m][2], a[m][3], b0, b1f);
            }
        }

        // Store fp16. Cols (2cA, 2cA+1) pack to one half2 uint.
        #pragma unroll
        for (int m = 0; m < 4; ++m) {
            int r0 = nb + m * 16 + g;
            #pragma unroll
            for (int n = 0; n < 2; ++n) {
                int hcol = (2 * w + n) * 4 + cA;
                if (r0 < n_nodes)
                    g_C[(size_t)r0 * 64 + hcol] = pack_h2(acc[m][n][0], acc[m][n][1]);
                if (r0 + 8 < n_nodes)
                    g_C[(size_t)(r0 + 8) * 64 + hcol] = pack_h2(acc[m][n][2], acc[m][n][3]);
            }
        }
    }
}

// ---------------------------------------------------------------------------
// Kernel 2: per-edge MLP, warp-autonomous 32-edge tiles, all-mma path
// (r10 structure, occ 4). ONLY change vs r10: uint2 pair loads for W2/W3
// fragments and float2 loads for b2/b3.
// ---------------------------------------------------------------------------
__global__ __launch_bounds__(256, 4) void edge_mlp_kernel(
    const int* __restrict__ src, const int* __restrict__ dst,
    const float* __restrict__ b2, const float* __restrict__ b3,
    float* __restrict__ out, int n_edges)
{
    extern __shared__ uint32_t smu[];
    uint32_t* Xs = smu;             // 8 warps * 32 * 36 uints

    const int tid  = threadIdx.x;
    const int lane = tid & 31;
    const int w    = tid >> 5;

    const int e0 = blockIdx.x * 256 + w * 32;
    const int eg = e0 + lane;
    const int s  = (eg < n_edges) ? src[eg] : 0;
    const int d  = (eg < n_edges) ? dst[eg] : 0;

    uint32_t* Xw = Xs + w * (32 * 36);
    const int q  = lane & 7;
    const int eh = lane >> 3;
    const uint4* Cu = (const uint4*)g_C;

    // Fused gather: X[el] = relu_h2(CA[src] + CB[dst])
    #pragma unroll
    for (int it = 0; it < 8; ++it) {
        int el   = it * 4 + eh;
        int srow = __shfl_sync(0xffffffffu, s, el);
        int drow = __shfl_sync(0xffffffffu, d, el);
        uint4 a = Cu[(size_t)srow * 16 + q];
        uint4 b = Cu[(size_t)drow * 16 + 8 + q];
        uint4 x;
        x.x = hadd_relu(a.x, b.x);
        x.y = hadd_relu(a.y, b.y);
        x.z = hadd_relu(a.z, b.z);
        x.w = hadd_relu(a.w, b.w);
        *(uint4*)(Xw + el * 36 + q * 4) = x;
    }
    __syncwarp();

    const int g  = lane >> 2;
    const int cA = lane & 3;

    // Layer 2: D[32x32] = X[32x64] @ W2T[64x32]; b2 as accumulator init
    float acc[2][4][4];
    #pragma unroll
    for (int n = 0; n < 4; ++n) {
        float2 bv = __ldg((const float2*)(b2 + n * 8 + 2 * cA));
        #pragma unroll
        for (int m = 0; m < 2; ++m) {
            acc[m][n][0] = bv.x; acc[m][n][1] = bv.y;
            acc[m][n][2] = bv.x; acc[m][n][3] = bv.y;
        }
    }

    uint32_t xw_addr = (uint32_t)__cvta_generic_to_shared(Xw);
    const int lrow  = (lane & 7) + ((lane >> 3) & 1) * 8;
    const int lcolh = (lane >> 4) * 8;
    uint32_t abase0 = xw_addr + (lrow * 36 + (lcolh >> 1)) * 4;   // m=0
    uint32_t abase1 = abase0 + 16 * 36 * 4;                       // m=1

    #pragma unroll
    for (int kt = 0; kt < 4; ++kt) {
        uint32_t A0[4], A1[4];
        ldsm_x4(A0[0], A0[1], A0[2], A0[3], abase0 + kt * 32);
        ldsm_x4(A1[0], A1[1], A1[2], A1[3], abase1 + kt * 32);
        #pragma unroll
        for (int n = 0; n < 4; ++n) {
            uint2 bf = __ldg((const uint2*)&g_W2h[(n * 4 + kt) * 64 + lane * 2]);
            mma_f16(acc[0][n][0], acc[0][n][1], acc[0][n][2], acc[0][n][3],
                    A0[0], A0[1], A0[2], A0[3], bf.x, bf.y);
            mma_f16(acc[1][n][0], acc[1][n][1], acc[1][n][2], acc[1][n][3],
                    A1[0], A1[1], A1[2], A1[3], bf.x, bf.y);
        }
    }

    // Layer 3 as mma: Z[32x8] = relu(Y)[32x32] @ W3T[32x8]; b3 as init.
    float zb0 = 0.f, zb1 = 0.f;
    if (cA < 3) {
        float2 bv = __ldg((const float2*)(b3 + 2 * cA));
        zb0 = bv.x; zb1 = bv.y;
    }
    float zc[2][4];
    #pragma unroll
    for (int m = 0; m < 2; ++m) {
        zc[m][0] = zb0; zc[m][1] = zb1; zc[m][2] = zb0; zc[m][3] = zb1;
    }

    uint2 w3f[2];
    w3f[0] = __ldg((const uint2*)&g_W3h[lane * 2]);
    w3f[1] = __ldg((const uint2*)&g_W3h[64 + lane * 2]);

    #pragma unroll
    for (int m = 0; m < 2; ++m)
        #pragma unroll
        for (int kt = 0; kt < 2; ++kt) {
            uint32_t a0 = pack_relu(acc[m][2 * kt][0],     acc[m][2 * kt][1]);
            uint32_t a1 = pack_relu(acc[m][2 * kt][2],     acc[m][2 * kt][3]);
            uint32_t a2 = pack_relu(acc[m][2 * kt + 1][0], acc[m][2 * kt + 1][1]);
            uint32_t a3 = pack_relu(acc[m][2 * kt + 1][2], acc[m][2 * kt + 1][3]);
            mma_f16(zc[m][0], zc[m][1], zc[m][2], zc[m][3],
                    a0, a1, a2, a3, w3f[kt].x, w3f[kt].y);
        }

    // Store: thread owns rows (m*16+g, +8), cols (2cA, 2cA+1); cA==3 -> pad
    if (cA < 3) {
        #pragma unroll
        for (int m = 0; m < 2; ++m) {
            int e1 = e0 + m * 16 + g;
            if (e1 < n_edges)
                *(float2*)&out[(size_t)e1 * 6 + 2 * cA] = make_float2(zc[m][0], zc[m][1]);
            int e2 = e1 + 8;
            if (e2 < n_edges)
                *(float2*)&out[(size_t)e2 * 6 + 2 * cA] = make_float2(zc[m][2], zc[m][3]);
        }
    }
}

// ---------------------------------------------------------------------------
// Launch
// ---------------------------------------------------------------------------
extern "C" void kernel_launch(void* const* d_in, const int* in_sizes, int n_in,
                              void* d_out, int out_size)
{
    const float* h   = (const float*)d_in[0];
    const int*   src = (const int*)  d_in[1];
    const int*   dst = (const int*)  d_in[2];
    const float* W1  = (const float*)d_in[3];
    const float* b1  = (const float*)d_in[4];
    const float* W2  = (const float*)d_in[5];
    const float* b2  = (const float*)d_in[6];
    const float* W3  = (const float*)d_in[7];
    const float* b3  = (const float*)d_in[8];
    float* out = (float*)d_out;

    const int n_nodes = in_sizes[0] / HF;
    const int n_edges = in_sizes[1];
    const int n_tiles = (n_nodes + 63) / 64;

    const int smem1 = (64 * HS2 + 8192) * 4;      // 50,176 B
    const int smem2 = (8 * 32 * 36) * 4;          // 36,864 B

    cudaFuncSetAttribute(precompute_kernel,
                         cudaFuncAttributeMaxDynamicSharedMemorySize, smem1);
    cudaFuncSetAttribute(edge_mlp_kernel,
                         cudaFuncAttributeMaxDynamicSharedMemorySize, smem2);

    init_frag_kernel<<<32, 256>>>(W1, W2, W3);
    precompute_kernel<<<PRE_GRID, 256, smem1>>>(h, b1, n_nodes, n_tiles);
    edge_mlp_kernel<<<(n_edges + 255) / 256, 256, smem2>>>(
        src, dst, b2, b3, out, n_edges);
}

// round 16
// speedup vs baseline: 1.5090x; 1.5090x over previous
#include <cuda_runtime.h>
#include <cuda_bf16.h>
#include <cuda_fp16.h>
#include <cstdint>

#define HF 128
#define MAX_NODES 100000

// Per-node precomputed layer-1 partials, fp16, b1 folded into A part:
// C[n][0:64] = h[n] @ W1[:, :128].T + b1 ; C[n][64:128] = h[n] @ W1[:, 128:].T
__device__ uint32_t g_C[(size_t)MAX_NODES * 64];
// One-shot fragment tables (fp16 half2, m16n8k16 B-frag order)
__device__ uint32_t g_Bh[8192];    // layer-1 weights G (128x128 rearranged W1)
__device__ uint32_t g_W2h[1024];   // layer-2 weights
__device__ uint32_t g_W3h[128];    // layer-3 weights (6 rows padded to 8)

__device__ __forceinline__ void mma_f16(float& c0, float& c1, float& c2, float& c3,
                                        uint32_t a0, uint32_t a1, uint32_t a2, uint32_t a3,
                                        uint32_t b0, uint32_t b1) {
    asm volatile(
        "mma.sync.aligned.m16n8k16.row.col.f32.f16.f16.f32 "
        "{%0,%1,%2,%3}, {%4,%5,%6,%7}, {%8,%9}, {%0,%1,%2,%3};"
        : "+f"(c0), "+f"(c1), "+f"(c2), "+f"(c3)
        : "r"(a0), "r"(a1), "r"(a2), "r"(a3), "r"(b0), "r"(b1));
}

__device__ __forceinline__ void ldsm_x4(uint32_t& r0, uint32_t& r1,
                                        uint32_t& r2, uint32_t& r3, uint32_t addr) {
    asm volatile("ldmatrix.sync.aligned.m8n8.x4.shared.b16 {%0,%1,%2,%3}, [%4];"
                 : "=r"(r0), "=r"(r1), "=r"(r2), "=r"(r3) : "r"(addr));
}

__device__ __forceinline__ uint32_t hadd_relu(uint32_t a, uint32_t b) {
    __half2 s = __hadd2(*(__half2*)&a, *(__half2*)&b);
    s = __hmax2(s, __half2half2(__float2half(0.f)));
    return *(uint32_t*)&s;
}

__device__ __forceinline__ uint32_t pack_h2(float x, float y) {
    __half2 v = __floats2half2_rn(x, y);
    return *(uint32_t*)&v;
}

__device__ __forceinline__ uint32_t pack_relu(float x, float y) {
    return pack_h2(fmaxf(x, 0.f), fmaxf(y, 0.f));
}

// ---------------------------------------------------------------------------
// Kernel 0: build fragment tables once (fp16 m16n8k16 B-frag order).
// Index law: entry (nt, kt, r, l): j = nt*8+(l>>2), kk = kt*16 + 2*(l&3) + r*8
// ---------------------------------------------------------------------------
__global__ void init_frag_kernel(const float* __restrict__ W1,
                                 const float* __restrict__ W2,
                                 const float* __restrict__ W3)
{
    int idx = blockIdx.x * 256 + threadIdx.x;
    if (idx < 8192) {
        int l  = idx & 31;
        int r  = (idx >> 5) & 1;
        int kt = (idx >> 6) & 7;
        int nt = idx >> 9;
        int j  = nt * 8 + (l >> 2);
        int kk = kt * 16 + 2 * (l & 3) + r * 8;
        float v0, v1;
        if (j < 64) { v0 = W1[j * 256 + kk];              v1 = W1[j * 256 + kk + 1]; }
        else        { v0 = W1[(j - 64) * 256 + 128 + kk]; v1 = W1[(j - 64) * 256 + 128 + kk + 1]; }
        g_Bh[idx] = pack_h2(v0, v1);
    }
    if (idx < 1024) {
        int l  = idx & 31;
        int r  = (idx >> 5) & 1;
        int kt = (idx >> 6) & 3;
        int nt = idx >> 8;
        int j  = nt * 8 + (l >> 2);
        int kk = kt * 16 + 2 * (l & 3) + r * 8;
        g_W2h[idx] = pack_h2(W2[j * 64 + kk], W2[j * 64 + kk + 1]);
    }
    if (idx < 128) {
        int l  = idx & 31;
        int r  = (idx >> 5) & 1;
        int kt = idx >> 6;
        int j  = l >> 2;                       // output class (pad 6,7 -> 0)
        int kk = kt * 16 + 2 * (l & 3) + r * 8;
        float v0 = (j < 6) ? W3[j * 32 + kk]     : 0.f;
        float v1 = (j < 6) ? W3[j * 32 + kk + 1] : 0.f;
        g_W3h[idx] = pack_h2(v0, v1);
    }
}

// ---------------------------------------------------------------------------
// Kernel 1: C = h @ G.T via fp16 mma, persistent blocks (Bh copied once per
// block from g_Bh table), b1 as accumulator init, fp16 store.
// ---------------------------------------------------------------------------
#define HS2 68
#define PRE_GRID 444   // 148 SMs * 3 blocks

__global__ __launch_bounds__(256, 3) void precompute_kernel(
    const float* __restrict__ h, const float* __restrict__ b1,
    int n_nodes, int n_tiles)
{
    extern __shared__ uint32_t smu[];
    uint32_t* hs = smu;              // [64][HS2] = 4352 uints
    uint32_t* Bh = smu + 64 * HS2;   // 8192 uints

    const int tid  = threadIdx.x;
    const int lane = tid & 31;
    const int w    = tid >> 5;

    // Copy Bh table once per block (coalesced uint4)
    {
        uint4* dstp = (uint4*)Bh;
        const uint4* srcp = (const uint4*)g_Bh;
        #pragma unroll
        for (int i = 0; i < 8; ++i)
            dstp[i * 256 + tid] = srcp[i * 256 + tid];
    }

    const int g  = lane >> 2;
    const int cA = lane & 3;

    // b1 fold (loop-invariant; A-part warps: w<4 -> cols 0..63)
    float bv0[2] = {0.f, 0.f}, bv1[2] = {0.f, 0.f};
    if (w < 4) {
        #pragma unroll
        for (int n = 0; n < 2; ++n) {
            int col = (2 * w + n) * 8 + 2 * cA;
            bv0[n] = b1[col];
            bv1[n] = b1[col + 1];
        }
    }

    for (int t = blockIdx.x; t < n_tiles; t += PRE_GRID) {
        const int nb = t * 64;
        __syncthreads();   // hs reusable (also orders Bh copy on 1st iter)

        // Stage 64 h rows as fp16
        #pragma unroll
        for (int i = 0; i < 8; ++i) {
            int idx = i * 256 + tid;
            int row = idx >> 5;
            int q   = idx & 31;
            int n   = nb + row;
            float4 v = make_float4(0.f, 0.f, 0.f, 0.f);
            if (n < n_nodes) v = ((const float4*)h)[(size_t)n * 32 + q];
            uint2 p = make_uint2(pack_h2(v.x, v.y), pack_h2(v.z, v.w));
            *(uint2*)(hs + row * HS2 + 2 * q) = p;
        }
        __syncthreads();

        float acc[4][2][4];
        #pragma unroll
        for (int m = 0; m < 4; ++m)
            #pragma unroll
            for (int n = 0; n < 2; ++n) {
                acc[m][n][0] = bv0[n]; acc[m][n][1] = bv1[n];
                acc[m][n][2] = bv0[n]; acc[m][n][3] = bv1[n];
            }

        #pragma unroll
        for (int kt = 0; kt < 8; ++kt) {
            uint32_t a[4][4];
            #pragma unroll
            for (int m = 0; m < 4; ++m) {
                int rA = m * 16 + g;
                a[m][0] = hs[rA * HS2 + kt * 8 + cA];
                a[m][1] = hs[(rA + 8) * HS2 + kt * 8 + cA];
                a[m][2] = hs[rA * HS2 + kt * 8 + cA + 4];
                a[m][3] = hs[(rA + 8) * HS2 + kt * 8 + cA + 4];
            }
            #pragma unroll
            for (int n = 0; n < 2; ++n) {
                int nt = 2 * w + n;
                uint32_t b0  = Bh[((nt * 8 + kt) * 2 + 0) * 32 + lane];
                uint32_t b1f = Bh[((nt * 8 + kt) * 2 + 1) * 32 + lane];
                #pragma unroll
                for (int m = 0; m < 4; ++m)
                    mma_f16(acc[m][n][0], acc[m][n][1], acc[m][n][2], acc[m][n][3],
                            a[m][0], a[m][1], a[m][2], a[m][3], b0, b1f);
            }
        }

        // Store fp16. Cols (2cA, 2cA+1) pack to one half2 uint.
        #pragma unroll
        for (int m = 0; m < 4; ++m) {
            int r0 = nb + m * 16 + g;
            #pragma unroll
            for (int n = 0; n < 2; ++n) {
                int hcol = (2 * w + n) * 4 + cA;
                if (r0 < n_nodes)
                    g_C[(size_t)r0 * 64 + hcol] = pack_h2(acc[m][n][0], acc[m][n][1]);
                if (r0 + 8 < n_nodes)
                    g_C[(size_t)(r0 + 8) * 64 + hcol] = pack_h2(acc[m][n][2], acc[m][n][3]);
            }
        }
    }
}

// ---------------------------------------------------------------------------
// Kernel 2: per-edge MLP, warp-autonomous 32-edge tiles, all-mma path.
// W2/W3 fragments read from L1-resident global tables; no block barrier.
// ---------------------------------------------------------------------------
__global__ __launch_bounds__(256, 4) void edge_mlp_kernel(
    const int* __restrict__ src, const int* __restrict__ dst,
    const float* __restrict__ b2, const float* __restrict__ b3,
    float* __restrict__ out, int n_edges)
{
    extern __shared__ uint32_t smu[];
    uint32_t* Xs = smu;             // 8 warps * 32 * 36 uints

    const int tid  = threadIdx.x;
    const int lane = tid & 31;
    const int w    = tid >> 5;

    const int e0 = blockIdx.x * 256 + w * 32;
    const int eg = e0 + lane;
    const int s  = (eg < n_edges) ? src[eg] : 0;
    const int d  = (eg < n_edges) ? dst[eg] : 0;

    uint32_t* Xw = Xs + w * (32 * 36);
    const int q  = lane & 7;
    const int eh = lane >> 3;
    const uint4* Cu = (const uint4*)g_C;

    // Fused gather: X[el] = relu_h2(CA[src] + CB[dst])
    #pragma unroll
    for (int it = 0; it < 8; ++it) {
        int el   = it * 4 + eh;
        int srow = __shfl_sync(0xffffffffu, s, el);
        int drow = __shfl_sync(0xffffffffu, d, el);
        uint4 a = Cu[(size_t)srow * 16 + q];
        uint4 b = Cu[(size_t)drow * 16 + 8 + q];
        uint4 x;
        x.x = hadd_relu(a.x, b.x);
        x.y = hadd_relu(a.y, b.y);
        x.z = hadd_relu(a.z, b.z);
        x.w = hadd_relu(a.w, b.w);
        *(uint4*)(Xw + el * 36 + q * 4) = x;
    }
    __syncwarp();

    const int g  = lane >> 2;
    const int cA = lane & 3;

    // Layer 2: D[32x32] = X[32x64] @ W2T[64x32]; b2 as accumulator init
    float acc[2][4][4];
    #pragma unroll
    for (int n = 0; n < 4; ++n) {
        int col = n * 8 + 2 * cA;
        float v0 = __ldg(b2 + col), v1 = __ldg(b2 + col + 1);
        #pragma unroll
        for (int m = 0; m < 2; ++m) {
            acc[m][n][0] = v0; acc[m][n][1] = v1;
            acc[m][n][2] = v0; acc[m][n][3] = v1;
        }
    }

    uint32_t xw_addr = (uint32_t)__cvta_generic_to_shared(Xw);
    const int lrow  = (lane & 7) + ((lane >> 3) & 1) * 8;
    const int lcolh = (lane >> 4) * 8;
    uint32_t abase0 = xw_addr + (lrow * 36 + (lcolh >> 1)) * 4;   // m=0
    uint32_t abase1 = abase0 + 16 * 36 * 4;                       // m=1

    #pragma unroll
    for (int kt = 0; kt < 4; ++kt) {
        uint32_t A0[4], A1[4];
        ldsm_x4(A0[0], A0[1], A0[2], A0[3], abase0 + kt * 32);
        ldsm_x4(A1[0], A1[1], A1[2], A1[3], abase1 + kt * 32);
        #pragma unroll
        for (int n = 0; n < 4; ++n) {
            uint32_t b0  = __ldg(&g_W2h[((n * 4 + kt) * 2 + 0) * 32 + lane]);
            uint32_t b1f = __ldg(&g_W2h[((n * 4 + kt) * 2 + 1) * 32 + lane]);
            mma_f16(acc[0][n][0], acc[0][n][1], acc[0][n][2], acc[0][n][3],
                    A0[0], A0[1], A0[2], A0[3], b0, b1f);
            mma_f16(acc[1][n][0], acc[1][n][1], acc[1][n][2], acc[1][n][3],
                    A1[0], A1[1], A1[2], A1[3], b0, b1f);
        }
    }

    // Layer 3 as mma: Z[32x8] = relu(Y)[32x32] @ W3T[32x8]; b3 as init.
    float zb0 = (cA < 3) ? __ldg(b3 + 2 * cA)     : 0.f;
    float zb1 = (cA < 3) ? __ldg(b3 + 2 * cA + 1) : 0.f;
    float zc[2][4];
    #pragma unroll
    for (int m = 0; m < 2; ++m) {
        zc[m][0] = zb0; zc[m][1] = zb1; zc[m][2] = zb0; zc[m][3] = zb1;
    }

    uint32_t w3f[2][2];
    #pragma unroll
    for (int kt = 0; kt < 2; ++kt) {
        w3f[kt][0] = __ldg(&g_W3h[(kt * 2 + 0) * 32 + lane]);
        w3f[kt][1] = __ldg(&g_W3h[(kt * 2 + 1) * 32 + lane]);
    }

    #pragma unroll
    for (int m = 0; m < 2; ++m)
        #pragma unroll
        for (int kt = 0; kt < 2; ++kt) {
            uint32_t a0 = pack_relu(acc[m][2 * kt][0],     acc[m][2 * kt][1]);
            uint32_t a1 = pack_relu(acc[m][2 * kt][2],     acc[m][2 * kt][3]);
            uint32_t a2 = pack_relu(acc[m][2 * kt + 1][0], acc[m][2 * kt + 1][1]);
            uint32_t a3 = pack_relu(acc[m][2 * kt + 1][2], acc[m][2 * kt + 1][3]);
            mma_f16(zc[m][0], zc[m][1], zc[m][2], zc[m][3],
                    a0, a1, a2, a3, w3f[kt][0], w3f[kt][1]);
        }

    // Store: thread owns rows (m*16+g, +8), cols (2cA, 2cA+1); cA==3 -> pad
    if (cA < 3) {
        #pragma unroll
        for (int m = 0; m < 2; ++m) {
            int e1 = e0 + m * 16 + g;
            if (e1 < n_edges)
                *(float2*)&out[(size_t)e1 * 6 + 2 * cA] = make_float2(zc[m][0], zc[m][1]);
            int e2 = e1 + 8;
            if (e2 < n_edges)
                *(float2*)&out[(size_t)e2 * 6 + 2 * cA] = make_float2(zc[m][2], zc[m][3]);
        }
    }
}

// ---------------------------------------------------------------------------
// Launch
// ---------------------------------------------------------------------------
extern "C" void kernel_launch(void* const* d_in, const int* in_sizes, int n_in,
                              void* d_out, int out_size)
{
    const float* h   = (const float*)d_in[0];
    const int*   src = (const int*)  d_in[1];
    const int*   dst = (const int*)  d_in[2];
    const float* W1  = (const float*)d_in[3];
    const float* b1  = (const float*)d_in[4];
    const float* W2  = (const float*)d_in[5];
    const float* b2  = (const float*)d_in[6];
    const float* W3  = (const float*)d_in[7];
    const float* b3  = (const float*)d_in[8];
    float* out = (float*)d_out;

    const int n_nodes = in_sizes[0] / HF;
    const int n_edges = in_sizes[1];
    const int n_tiles = (n_nodes + 63) / 64;

    const int smem1 = (64 * HS2 + 8192) * 4;      // 50,176 B
    const int smem2 = (8 * 32 * 36) * 4;          // 36,864 B

    cudaFuncSetAttribute(precompute_kernel,
                         cudaFuncAttributeMaxDynamicSharedMemorySize, smem1);
    cudaFuncSetAttribute(edge_mlp_kernel,
                         cudaFuncAttributeMaxDynamicSharedMemorySize, smem2);

    init_frag_kernel<<<32, 256>>>(W1, W2, W3);
    precompute_kernel<<<PRE_GRID, 256, smem1>>>(h, b1, n_nodes, n_tiles);
    edge_mlp_kernel<<<(n_edges + 255) / 256, 256, smem2>>>(
        src, dst, b2, b3, out, n_edges);
}